// round 13
// baseline (speedup 1.0000x reference)
#include <cuda_runtime.h>
#include <cuda_fp16.h>
#include <cstdint>

// ---------------------------------------------------------------- constants
#define B_     64
#define T_     16
#define IMG_   84
#define FR_    7056         // 84*84
#define P_     7
#define NS_    144
#define K_     98
#define KP_    128          // physical row width (halves)
#define KSTEPS 6            // tensor path: 6 x k16 = 96; k=96,97 via FFMA
#define E_     1024
#define NTOK_  1152
#define M_     73728

// Swizzled scratch: within each 128-half row, 16B chunk c lives at c ^ (row&7).
__device__ __half g_A[(size_t)M_ * KP_];   // [m][128]  18.9 MB
__device__ __half g_B[(size_t)E_ * KP_];   // [e][128]  256 KB

// ---------------------------------------------------------------- helpers
__device__ __forceinline__ void mma_f16(float4& d, const uint32_t a[4],
                                        const uint32_t b[2]) {
    asm("mma.sync.aligned.m16n8k16.row.col.f32.f16.f16.f32 "
        "{%0,%1,%2,%3}, {%4,%5,%6,%7}, {%8,%9}, {%0,%1,%2,%3};"
        : "+f"(d.x), "+f"(d.y), "+f"(d.z), "+f"(d.w)
        : "r"(a[0]), "r"(a[1]), "r"(a[2]), "r"(a[3]), "r"(b[0]), "r"(b[1]));
}
__device__ __forceinline__ uint32_t smem_u32(const void* p) {
    uint32_t a;
    asm("{ .reg .u64 t; cvta.to.shared.u64 t, %1; cvt.u32.u64 %0, t; }"
        : "=r"(a) : "l"(p));
    return a;
}
#define MBAR_INIT(mb, c) \
    asm volatile("mbarrier.init.shared.b64 [%0], %1;" \
                 :: "r"((uint32_t)(mb)), "r"((uint32_t)(c)) : "memory")
#define MBAR_EXPECT_TX(mb, n) \
    asm volatile("mbarrier.arrive.expect_tx.shared.b64 _, [%0], %1;" \
                 :: "r"((uint32_t)(mb)), "r"((uint32_t)(n)) : "memory")
#define MBAR_WAIT(mb, ph) do {                                                    \
    uint32_t _mb = (uint32_t)(mb); uint32_t _ph = (uint32_t)(ph); uint32_t _done; \
    asm volatile("{\n\t.reg .pred p;\n\t"                                         \
        "mbarrier.try_wait.parity.acquire.cta.shared::cta.b64 p, [%1], %2;\n\t"   \
        "selp.b32 %0, 1, 0, p;\n\t}" : "=r"(_done) : "r"(_mb), "r"(_ph) : "memory"); \
    if (!_done) {                                                                 \
        asm volatile("{\n\t.reg .pred P1;\n\t"                                    \
            "WL_%=:\n\t"                                                          \
            "mbarrier.try_wait.parity.acquire.cta.shared::cta.b64 P1, [%0], %1, 0x989680;\n\t" \
            "@P1 bra.uni WD_%=;\n\t"                                              \
            "bra.uni WL_%=;\n\t"                                                  \
            "WD_%=:\n\t}" :: "r"(_mb), "r"(_ph) : "memory");                      \
    }                                                                             \
} while (0)
__device__ __forceinline__ void bulk_g2s(uint32_t dst, const void* src,
                                         uint32_t bytes, uint32_t mbar) {
    asm volatile(
        "cp.async.bulk.shared::cta.global.mbarrier::complete_tx::bytes "
        "[%0], [%1], %2, [%3];"
        :: "r"(dst), "l"(src), "r"(bytes), "r"(mbar) : "memory");
}

// ---------------------------------------------------------------- prep
// blocks [0,1024): gather. block = (b, d, s-half). 42 pixel rows of both
// tubelet frames cached as fp16 (14 KB). One 16B g_A chunk per work unit.
// blocks [1024,1056): W -> g_B fp16 with the same swizzle.
#define GROWS 42            // pixel rows per half
#define GHALF (GROWS * IMG_)   // 3528 pixels
__global__ void prep_kernel(const float* __restrict__ video,
                            const float* __restrict__ W) {
    int blk = blockIdx.x;
    if (blk >= 1024) {                        // ---- W conversion ----
        for (int idx = (blk - 1024) * 256 + threadIdx.x; idx < E_ * K_;
             idx += 32 * 256) {
            int e = idx / K_, k = idx - e * K_;
            int ph = (((k >> 3) ^ (e & 7)) << 3) | (k & 7);
            g_B[(size_t)e * KP_ + ph] = __float2half_rn(W[idx]);
        }
        return;
    }
    // ---- gather ----
    extern __shared__ __half fr[];            // [2][GHALF]
    int b = blk >> 4, dh = blk & 15;
    int d = dh >> 1, half = dh & 1;
    const float* src = video + (size_t)(b * T_ + d * 2) * FR_ + half * GHALF;
    for (int i = threadIdx.x; i < (2 * GHALF) / 4; i += blockDim.x) {
        int f = i / (GHALF / 4);              // frame 0/1
        int j = i - f * (GHALF / 4);
        float4 v = *(const float4*)(src + (size_t)f * FR_ + j * 4);
        __half h[4] = {__float2half_rn(v.x), __float2half_rn(v.y),
                       __float2half_rn(v.z), __float2half_rn(v.w)};
        *(uint2*)(&fr[f * GHALF + j * 4]) = *(const uint2*)h;
    }
    __syncthreads();

    int mbase = b * NTOK_ + d * NS_;
    for (int u = threadIdx.x; u < 72 * 13; u += blockDim.x) {
        int sl = u / 13, c = u - sl * 13;     // chunk c covers kk = 8c..8c+7
        int s  = half * 72 + sl;
        int hl = sl / 12, w = sl - hl * 12;   // local patch row 0..5
        const __half* f0 = fr + hl * (P_ * IMG_) + w * P_;
        __half hv[8];
#pragma unroll
        for (int j = 0; j < 8; ++j) {
            int kk = c * 8 + j;
            __half v = __ushort_as_half((unsigned short)0);
            if (kk < K_) {
                int ts = kk >= 49;
                int k  = kk - ts * 49;
                int pi = k / P_, pj = k - pi * P_;
                v = f0[ts * GHALF + pi * IMG_ + pj];
            }
            hv[j] = v;
        }
        int ph = c ^ (s & 7);                 // (mbase+s)&7 == s&7
        *(uint4*)(&g_A[(size_t)(mbase + s) * KP_ + ph * 8]) = *(const uint4*)hv;
    }
}

// ---------------------------------------------------------------- GEMM
// Persistent-strip GEMM: grid 8(e) x 18(strips). B loaded once per CTA;
// 16 m-tiles of 256x128 pipelined with double-buffered bulk-copied A
// (prefetch distance 2, per-64-row-quarter barriers so each warp starts
// as soon as ITS quarter lands). K=96 tensor + FFMA tail (k=96,97).
#define MT      256
#define ET      128
#define TILES   16
#define SBB     (ET * KP_)              // B halves (32 KB)
#define SAB     (MT * KP_)              // A halves per buffer (64 KB)
#define QBYTES  (64 * KP_ * 2)          // one A quarter (16 KB)
#define SMEM_BYTES ((SBB + 2 * SAB) * 2)   // 163840 B

__global__ __launch_bounds__(256, 1)
void gemm_kernel(const float* __restrict__ bias,
                 const float* __restrict__ pos,
                 float* __restrict__ out) {
    extern __shared__ __half sm[];
    __half* sB = sm;                   // [128][128] swizzled rows
    __half* sA[2] = {sm + SBB, sm + SBB + SAB};
    __shared__ __align__(8) unsigned long long bars[9];  // B, A[buf][q]

    const int tid  = threadIdx.x;
    const int lane = tid & 31;
    const int wid  = tid >> 5;
    const int grp  = lane >> 2;        // 0..7
    const int tg   = lane & 3;         // 0..3
    const int wm   = wid & 3;          // m-quarter -> wm*64
    const int wn   = wid >> 2;         // e-half    -> wn*64

    const int e0 = blockIdx.x * ET;
    const int j0 = blockIdx.y * TILES; // first m-tile index

    const uint32_t barB = smem_u32(&bars[0]);
    auto barA = [&](int buf, int q) { return smem_u32(&bars[1 + buf * 4 + q]); };

    if (tid == 0) {
#pragma unroll
        for (int q = 0; q < 9; ++q) MBAR_INIT(smem_u32(&bars[q]), 1);
    }
    __syncthreads();

    auto stage_tile = [&](int tile, int buf) {   // 4 quarter copies
        const __half* src = g_A + (size_t)tile * MT * KP_;
        uint32_t dst = smem_u32(sA[buf]);
#pragma unroll
        for (int q = 0; q < 4; ++q) {
            MBAR_EXPECT_TX(barA(buf, q), QBYTES);
            bulk_g2s(dst + q * QBYTES, src + (size_t)q * 64 * KP_,
                     QBYTES, barA(buf, q));
        }
    };

    if (tid == 0) {
        MBAR_EXPECT_TX(barB, SBB * 2);
        bulk_g2s(smem_u32(sB), g_B + (size_t)e0 * KP_, SBB * 2, barB);
        stage_tile(j0, 0);
        stage_tile(j0 + 1, 1);
    }

    MBAR_WAIT(barB, 0);
    const __half* wB = sB + (wn * 64 + grp) * KP_;

#pragma unroll 1
    for (int i = 0; i < TILES; ++i) {
        const int buf = i & 1;
        MBAR_WAIT(barA(buf, wm), (i >> 1) & 1);  // only this warp's quarter

        const int m0 = (j0 + i) * MT;
        const __half* wA = sA[buf] + (wm * 64 + grp) * KP_;

        // epilogue coordinates for this tile
        const int n0 = m0 % NTOK_;
        int mg[4], ng0[4], ng1[4];
#pragma unroll
        for (int mf = 0; mf < 4; ++mf) {
            int rl = wm * 64 + mf * 16 + grp;
            mg[mf] = m0 + rl;
            int n  = n0 + rl;      if (n  >= NTOK_) n  -= NTOK_;
            int n2 = n0 + rl + 8;  if (n2 >= NTOK_) n2 -= NTOK_;
            ng0[mf] = n; ng1[mf] = n2;
        }

        // A operands for the k=96,97 FFMA tail (chunk 12)
        float2 ca0[4], ca1[4];
        {
            const int ca = (12 ^ grp) << 3;
#pragma unroll
            for (int mf = 0; mf < 4; ++mf) {
                ca0[mf] = __half22float2(*(const __half2*)(wA + mf * 16 * KP_ + ca));
                ca1[mf] = __half22float2(*(const __half2*)(wA + (mf * 16 + 8) * KP_ + ca));
            }
        }

#pragma unroll
        for (int half = 0; half < 2; ++half) {
            const int nb = half * 4;
            float4 acc[4][4];
#pragma unroll
            for (int a = 0; a < 4; ++a)
#pragma unroll
                for (int b = 0; b < 4; ++b) acc[a][b] = make_float4(0.f, 0.f, 0.f, 0.f);

#pragma unroll
            for (int ks = 0; ks < KSTEPS; ++ks) {
                const int off0 = (((2 * ks)     ^ grp) << 3) + tg * 2;
                const int off1 = (((2 * ks + 1) ^ grp) << 3) + tg * 2;

                uint32_t af[4][4], bf[4][2];
#pragma unroll
                for (int mf = 0; mf < 4; ++mf) {
                    const __half* r0 = wA + mf * 16 * KP_;
                    af[mf][0] = *(const uint32_t*)(r0 + off0);
                    af[mf][1] = *(const uint32_t*)(r0 + 8 * KP_ + off0);
                    af[mf][2] = *(const uint32_t*)(r0 + off1);
                    af[mf][3] = *(const uint32_t*)(r0 + 8 * KP_ + off1);
                }
#pragma unroll
                for (int nf = 0; nf < 4; ++nf) {
                    const __half* r0 = wB + (nb + nf) * 8 * KP_;
                    bf[nf][0] = *(const uint32_t*)(r0 + off0);
                    bf[nf][1] = *(const uint32_t*)(r0 + off1);
                }
#pragma unroll
                for (int mf = 0; mf < 4; ++mf)
#pragma unroll
                    for (int nf = 0; nf < 4; ++nf)
                        mma_f16(acc[mf][nf], af[mf], bf[nf]);
            }

            // FFMA tail: kk = 96,97 on the fp32 pipe
#pragma unroll
            for (int nf = 0; nf < 4; ++nf) {
                int er = wn * 64 + (nb + nf) * 8 + 2 * tg;
                const __half* bp0 = sB + (size_t)er * KP_ + ((12 ^ (er & 7)) << 3);
                const __half* bp1 = sB + (size_t)(er + 1) * KP_ + ((12 ^ ((er + 1) & 7)) << 3);
                float2 b0 = __half22float2(*(const __half2*)bp0);
                float2 b1 = __half22float2(*(const __half2*)bp1);
#pragma unroll
                for (int mf = 0; mf < 4; ++mf) {
                    float4& a = acc[mf][nf];
                    a.x += ca0[mf].x * b0.x + ca0[mf].y * b0.y;
                    a.y += ca0[mf].x * b1.x + ca0[mf].y * b1.y;
                    a.z += ca1[mf].x * b0.x + ca1[mf].y * b0.y;
                    a.w += ca1[mf].x * b1.x + ca1[mf].y * b1.y;
                }
            }

            // epilogue: out = acc + bias + pos
            const int colb = e0 + wn * 64 + nb * 8 + tg * 2;
#pragma unroll
            for (int mf = 0; mf < 4; ++mf) {
                const float* pr0 = pos + (size_t)ng0[mf] * E_ + colb;
                const float* pr1 = pos + (size_t)ng1[mf] * E_ + colb;
                float* or0 = out + (size_t)mg[mf] * E_ + colb;
                float* or1 = or0 + 8 * E_;
#pragma unroll
                for (int nf = 0; nf < 4; ++nf) {
                    float2 bb = *(const float2*)(bias + colb + nf * 8);
                    float2 p0 = *(const float2*)(pr0 + nf * 8);
                    float2 p1 = *(const float2*)(pr1 + nf * 8);
                    float4 a  = acc[mf][nf];
                    float2 o0 = make_float2(a.x + bb.x + p0.x, a.y + bb.y + p0.y);
                    float2 o1 = make_float2(a.z + bb.x + p1.x, a.w + bb.y + p1.y);
                    __stcs((float2*)(or0 + nf * 8), o0);
                    __stcs((float2*)(or1 + nf * 8), o1);
                }
            }
        }

        // all warps finished reading buffer `buf` -> refill it 2 tiles ahead
        __syncthreads();
        if (tid == 0 && i + 2 < TILES) stage_tile(j0 + i + 2, buf);
    }
}

// ---------------------------------------------------------------- launch
extern "C" void kernel_launch(void* const* d_in, const int* in_sizes, int n_in,
                              void* d_out, int out_size) {
    const float* video = (const float*)d_in[0];   // [64,16,1,84,84]
    const float* W     = (const float*)d_in[1];   // [1024,98]
    const float* bias  = (const float*)d_in[2];   // [1024]
    const float* pos   = (const float*)d_in[3];   // [1,1152,1024]
    float* out         = (float*)d_out;           // [64,1152,1024]

    cudaFuncSetAttribute(gemm_kernel, cudaFuncAttributeMaxDynamicSharedMemorySize,
                         SMEM_BYTES);
    cudaFuncSetAttribute(prep_kernel, cudaFuncAttributeMaxDynamicSharedMemorySize,
                         2 * GHALF * 2);

    prep_kernel<<<1024 + 32, 256, 2 * GHALF * 2>>>(video, W);
    gemm_kernel<<<dim3(E_ / ET, M_ / (MT * TILES)), 256, SMEM_BYTES>>>(bias, pos, out);
}

// round 14
// speedup vs baseline: 1.1591x; 1.1591x over previous
#include <cuda_runtime.h>
#include <cuda_fp16.h>
#include <cstdint>

// ---------------------------------------------------------------- constants
#define B_     64
#define T_     16
#define IMG_   84
#define FR_    7056         // 84*84
#define P_     7
#define NS_    144
#define K_     98
#define KP_    128          // physical row width (halves)
#define KSTEPS 6            // tensor path: 6 x k16 = 96; k=96,97 via FFMA
#define E_     1024
#define NTOK_  1152
#define M_     73728

// Swizzled scratch: within each 128-half row, 16B chunk c lives at c ^ (row&7).
__device__ __half g_A[(size_t)M_ * KP_];   // [m][128]  18.9 MB
__device__ __half g_B[(size_t)E_ * KP_];   // [e][128]  256 KB

// ---------------------------------------------------------------- helpers
__device__ __forceinline__ void mma_f16(float4& d, const uint32_t a[4],
                                        const uint32_t b[2]) {
    asm("mma.sync.aligned.m16n8k16.row.col.f32.f16.f16.f32 "
        "{%0,%1,%2,%3}, {%4,%5,%6,%7}, {%8,%9}, {%0,%1,%2,%3};"
        : "+f"(d.x), "+f"(d.y), "+f"(d.z), "+f"(d.w)
        : "r"(a[0]), "r"(a[1]), "r"(a[2]), "r"(a[3]), "r"(b[0]), "r"(b[1]));
}
__device__ __forceinline__ void ldsm_x4(uint32_t a[4], uint32_t addr) {
    asm volatile("ldmatrix.sync.aligned.m8n8.x4.shared.b16 {%0,%1,%2,%3}, [%4];"
                 : "=r"(a[0]), "=r"(a[1]), "=r"(a[2]), "=r"(a[3]) : "r"(addr));
}
__device__ __forceinline__ void ldsm_x2(uint32_t a[2], uint32_t addr) {
    asm volatile("ldmatrix.sync.aligned.m8n8.x2.shared.b16 {%0,%1}, [%2];"
                 : "=r"(a[0]), "=r"(a[1]) : "r"(addr));
}
__device__ __forceinline__ uint32_t smem_u32(const void* p) {
    uint32_t a;
    asm("{ .reg .u64 t; cvta.to.shared.u64 t, %1; cvt.u32.u64 %0, t; }"
        : "=r"(a) : "l"(p));
    return a;
}
#define MBAR_INIT(mb, c) \
    asm volatile("mbarrier.init.shared.b64 [%0], %1;" \
                 :: "r"((uint32_t)(mb)), "r"((uint32_t)(c)) : "memory")
#define MBAR_EXPECT_TX(mb, n) \
    asm volatile("mbarrier.arrive.expect_tx.shared.b64 _, [%0], %1;" \
                 :: "r"((uint32_t)(mb)), "r"((uint32_t)(n)) : "memory")
#define MBAR_WAIT(mb, ph) do {                                                    \
    uint32_t _mb = (uint32_t)(mb); uint32_t _ph = (uint32_t)(ph); uint32_t _done; \
    asm volatile("{\n\t.reg .pred p;\n\t"                                         \
        "mbarrier.try_wait.parity.acquire.cta.shared::cta.b64 p, [%1], %2;\n\t"   \
        "selp.b32 %0, 1, 0, p;\n\t}" : "=r"(_done) : "r"(_mb), "r"(_ph) : "memory"); \
    if (!_done) {                                                                 \
        asm volatile("{\n\t.reg .pred P1;\n\t"                                    \
            "WL_%=:\n\t"                                                          \
            "mbarrier.try_wait.parity.acquire.cta.shared::cta.b64 P1, [%0], %1, 0x989680;\n\t" \
            "@P1 bra.uni WD_%=;\n\t"                                              \
            "bra.uni WL_%=;\n\t"                                                  \
            "WD_%=:\n\t}" :: "r"(_mb), "r"(_ph) : "memory");                      \
    }                                                                             \
} while (0)
__device__ __forceinline__ void bulk_g2s(uint32_t dst, const void* src,
                                         uint32_t bytes, uint32_t mbar) {
    asm volatile(
        "cp.async.bulk.shared::cta.global.mbarrier::complete_tx::bytes "
        "[%0], [%1], %2, [%3];"
        :: "r"(dst), "l"(src), "r"(bytes), "r"(mbar) : "memory");
}

// ---------------------------------------------------------------- prep
// blocks [0,1024): gather, block = (b, d, s-half), 14 KB fp16 frame cache.
// blocks [1024,1056): W -> g_B fp16 with the same swizzle.
#define GROWS 42            // pixel rows per half
#define GHALF (GROWS * IMG_)   // 3528 pixels
__global__ void prep_kernel(const float* __restrict__ video,
                            const float* __restrict__ W) {
    int blk = blockIdx.x;
    if (blk >= 1024) {                        // ---- W conversion ----
        for (int idx = (blk - 1024) * 256 + threadIdx.x; idx < E_ * K_;
             idx += 32 * 256) {
            int e = idx / K_, k = idx - e * K_;
            int ph = (((k >> 3) ^ (e & 7)) << 3) | (k & 7);
            g_B[(size_t)e * KP_ + ph] = __float2half_rn(W[idx]);
        }
        return;
    }
    // ---- gather ----
    extern __shared__ __half fr[];            // [2][GHALF]
    int b = blk >> 4, dh = blk & 15;
    int d = dh >> 1, half = dh & 1;
    const float* src = video + (size_t)(b * T_ + d * 2) * FR_ + half * GHALF;
    for (int i = threadIdx.x; i < (2 * GHALF) / 4; i += blockDim.x) {
        int f = i / (GHALF / 4);              // frame 0/1
        int j = i - f * (GHALF / 4);
        float4 v = *(const float4*)(src + (size_t)f * FR_ + j * 4);
        __half h[4] = {__float2half_rn(v.x), __float2half_rn(v.y),
                       __float2half_rn(v.z), __float2half_rn(v.w)};
        *(uint2*)(&fr[f * GHALF + j * 4]) = *(const uint2*)h;
    }
    __syncthreads();

    int mbase = b * NTOK_ + d * NS_;
    for (int u = threadIdx.x; u < 72 * 13; u += blockDim.x) {
        int sl = u / 13, c = u - sl * 13;     // chunk c covers kk = 8c..8c+7
        int s  = half * 72 + sl;
        int hl = sl / 12, w = sl - hl * 12;
        const __half* f0 = fr + hl * (P_ * IMG_) + w * P_;
        __half hv[8];
#pragma unroll
        for (int j = 0; j < 8; ++j) {
            int kk = c * 8 + j;
            __half v = __ushort_as_half((unsigned short)0);
            if (kk < K_) {
                int ts = kk >= 49;
                int k  = kk - ts * 49;
                int pi = k / P_, pj = k - pi * P_;
                v = f0[ts * GHALF + pi * IMG_ + pj];
            }
            hv[j] = v;
        }
        int ph = c ^ (s & 7);                 // (mbase+s)&7 == s&7
        *(uint4*)(&g_A[(size_t)(mbase + s) * KP_ + ph * 8]) = *(const uint4*)hv;
    }
}

// ---------------------------------------------------------------- GEMM
// Persistent-strip GEMM (R11 skeleton): grid 8(e) x 18(strips), B loaded once,
// 16 m-tiles of 256x128 double-buffered via bulk copies. Fragments loaded with
// ldmatrix (LDSM.x4 for A, LDSM.x2 for B) -> 3x fewer shared-load issues.
#define MT      256
#define ET      128
#define TILES   16
#define SBB     (ET * KP_)              // B halves (32 KB)
#define SAB     (MT * KP_)              // A halves per buffer (64 KB)
#define ATILE_BYTES (SAB * 2)
#define SMEM_BYTES ((SBB + 2 * SAB) * 2)   // 163840 B

__global__ __launch_bounds__(256, 1)
void gemm_kernel(const float* __restrict__ bias,
                 const float* __restrict__ pos,
                 float* __restrict__ out) {
    extern __shared__ __half sm[];
    __half* sB = sm;                   // [128][128] swizzled rows
    __half* sA0 = sm + SBB;
    __half* sA1 = sA0 + SAB;
    __shared__ __align__(8) unsigned long long bars[3];  // B, A0, A1

    const int tid  = threadIdx.x;
    const int lane = tid & 31;
    const int wid  = tid >> 5;
    const int grp  = lane >> 2;        // 0..7
    const int tg   = lane & 3;         // 0..3
    const int wm   = wid & 3;          // m-quarter -> wm*64
    const int wn   = wid >> 2;         // e-half    -> wn*64

    const int e0 = blockIdx.x * ET;
    const int j0 = blockIdx.y * TILES; // first m-tile index

    const uint32_t barB  = smem_u32(&bars[0]);
    const uint32_t barA0 = smem_u32(&bars[1]);
    const uint32_t barA1 = smem_u32(&bars[2]);

    if (tid == 0) {
        MBAR_INIT(barB, 1);
        MBAR_INIT(barA0, 1);
        MBAR_INIT(barA1, 1);
    }
    __syncthreads();

    if (tid == 0) {
        MBAR_EXPECT_TX(barB, SBB * 2);
        bulk_g2s(smem_u32(sB), g_B + (size_t)e0 * KP_, SBB * 2, barB);
        MBAR_EXPECT_TX(barA0, ATILE_BYTES);
        bulk_g2s(smem_u32(sA0), g_A + (size_t)j0 * MT * KP_, ATILE_BYTES, barA0);
        MBAR_EXPECT_TX(barA1, ATILE_BYTES);
        bulk_g2s(smem_u32(sA1), g_A + (size_t)(j0 + 1) * MT * KP_, ATILE_BYTES, barA1);
    }

    // ---- ldmatrix per-lane address components ----
    // A (x4): quad 0..3 -> (m_local 0-7 / 8-15) x (k8-chunk 0/1)
    const int aql  = lane & 7;                   // row within 8
    const int aqm  = ((lane >> 3) & 1) * 8;      // +8 rows for quads 1,3
    const int akc  = lane >> 4;                  // k8 chunk 0/1
    const uint32_t arl16 = (uint32_t)aql << 4;   // swizzle term
    // A row (within tile) for this lane at fragment mf: wm*64 + mf*16 + aqm + aql
    // B (x2): lanes 0-7 k-lo, 8-15 k-hi (lanes 16-31 addrs ignored; keep valid)
    const int bql  = lane & 7;
    const int bkc  = (lane >> 3) & 1;
    const uint32_t brl16 = (uint32_t)bql << 4;
    const uint32_t uB = smem_u32(sB) + (uint32_t)(wn * 64 + bql) * (KP_ * 2);

    MBAR_WAIT(barB, 0);

#pragma unroll 1
    for (int i = 0; i < TILES; ++i) {
        const int buf = i & 1;
        const uint32_t barA = buf ? barA1 : barA0;
        __half* sA = buf ? sA1 : sA0;
        MBAR_WAIT(barA, (i >> 1) & 1);

        const int m0 = (j0 + i) * MT;
        const __half* wA = sA + (wm * 64 + grp) * KP_;   // for FFMA tail
        const uint32_t uA = smem_u32(sA) +
            (uint32_t)(wm * 64 + aqm + aql) * (KP_ * 2);

        // epilogue coordinates for this tile
        const int n0 = m0 % NTOK_;
        int mg[4], ng0[4], ng1[4];
#pragma unroll
        for (int mf = 0; mf < 4; ++mf) {
            int rl = wm * 64 + mf * 16 + grp;
            mg[mf] = m0 + rl;
            int n  = n0 + rl;      if (n  >= NTOK_) n  -= NTOK_;
            int n2 = n0 + rl + 8;  if (n2 >= NTOK_) n2 -= NTOK_;
            ng0[mf] = n; ng1[mf] = n2;
        }

        // A operands for the k=96,97 FFMA tail (chunk 12)
        float2 ca0[4], ca1[4];
        {
            const int ca = (12 ^ grp) << 3;
#pragma unroll
            for (int mf = 0; mf < 4; ++mf) {
                ca0[mf] = __half22float2(*(const __half2*)(wA + mf * 16 * KP_ + ca));
                ca1[mf] = __half22float2(*(const __half2*)(wA + (mf * 16 + 8) * KP_ + ca));
            }
        }

#pragma unroll
        for (int half = 0; half < 2; ++half) {
            const int nb = half * 4;
            float4 acc[4][4];
#pragma unroll
            for (int a = 0; a < 4; ++a)
#pragma unroll
                for (int b = 0; b < 4; ++b) acc[a][b] = make_float4(0.f, 0.f, 0.f, 0.f);

#pragma unroll
            for (int ks = 0; ks < KSTEPS; ++ks) {
                uint32_t af[4][4], bf[4][2];
                const uint32_t offA = (uint32_t)(((2 * ks + akc) << 4)) ^ arl16;
                const uint32_t offB = (uint32_t)(((2 * ks + bkc) << 4)) ^ brl16;
#pragma unroll
                for (int mf = 0; mf < 4; ++mf)
                    ldsm_x4(af[mf], uA + (uint32_t)mf * (16 * KP_ * 2) + offA);
#pragma unroll
                for (int nf = 0; nf < 4; ++nf)
                    ldsm_x2(bf[nf], uB + (uint32_t)((nb + nf) * 8) * (KP_ * 2) + offB);
#pragma unroll
                for (int mf = 0; mf < 4; ++mf)
#pragma unroll
                    for (int nf = 0; nf < 4; ++nf)
                        mma_f16(acc[mf][nf], af[mf], bf[nf]);
            }

            // FFMA tail: kk = 96,97 on the fp32 pipe
#pragma unroll
            for (int nf = 0; nf < 4; ++nf) {
                int er = wn * 64 + (nb + nf) * 8 + 2 * tg;
                const __half* bp0 = sB + (size_t)er * KP_ + ((12 ^ (er & 7)) << 3);
                const __half* bp1 = sB + (size_t)(er + 1) * KP_ + ((12 ^ ((er + 1) & 7)) << 3);
                float2 b0 = __half22float2(*(const __half2*)bp0);
                float2 b1 = __half22float2(*(const __half2*)bp1);
#pragma unroll
                for (int mf = 0; mf < 4; ++mf) {
                    float4& a = acc[mf][nf];
                    a.x += ca0[mf].x * b0.x + ca0[mf].y * b0.y;
                    a.y += ca0[mf].x * b1.x + ca0[mf].y * b1.y;
                    a.z += ca1[mf].x * b0.x + ca1[mf].y * b0.y;
                    a.w += ca1[mf].x * b1.x + ca1[mf].y * b1.y;
                }
            }

            // epilogue: out = acc + bias + pos
            const int colb = e0 + wn * 64 + nb * 8 + tg * 2;
#pragma unroll
            for (int mf = 0; mf < 4; ++mf) {
                const float* pr0 = pos + (size_t)ng0[mf] * E_ + colb;
                const float* pr1 = pos + (size_t)ng1[mf] * E_ + colb;
                float* or0 = out + (size_t)mg[mf] * E_ + colb;
                float* or1 = or0 + 8 * E_;
#pragma unroll
                for (int nf = 0; nf < 4; ++nf) {
                    float2 bb = *(const float2*)(bias + colb + nf * 8);
                    float2 p0 = *(const float2*)(pr0 + nf * 8);
                    float2 p1 = *(const float2*)(pr1 + nf * 8);
                    float4 a  = acc[mf][nf];
                    float2 o0 = make_float2(a.x + bb.x + p0.x, a.y + bb.y + p0.y);
                    float2 o1 = make_float2(a.z + bb.x + p1.x, a.w + bb.y + p1.y);
                    __stcs((float2*)(or0 + nf * 8), o0);
                    __stcs((float2*)(or1 + nf * 8), o1);
                }
            }
        }

        // all warps finished reading buffer `buf` -> refill it 2 tiles ahead
        __syncthreads();
        if (tid == 0 && i + 2 < TILES) {
            MBAR_EXPECT_TX(barA, ATILE_BYTES);
            bulk_g2s(smem_u32(sA), g_A + (size_t)(j0 + i + 2) * MT * KP_,
                     ATILE_BYTES, barA);
        }
    }
}

// ---------------------------------------------------------------- launch
extern "C" void kernel_launch(void* const* d_in, const int* in_sizes, int n_in,
                              void* d_out, int out_size) {
    const float* video = (const float*)d_in[0];   // [64,16,1,84,84]
    const float* W     = (const float*)d_in[1];   // [1024,98]
    const float* bias  = (const float*)d_in[2];   // [1024]
    const float* pos   = (const float*)d_in[3];   // [1,1152,1024]
    float* out         = (float*)d_out;           // [64,1152,1024]

    cudaFuncSetAttribute(gemm_kernel, cudaFuncAttributeMaxDynamicSharedMemorySize,
                         SMEM_BYTES);
    cudaFuncSetAttribute(prep_kernel, cudaFuncAttributeMaxDynamicSharedMemorySize,
                         2 * GHALF * 2);

    prep_kernel<<<1024 + 32, 256, 2 * GHALF * 2>>>(video, W);
    gemm_kernel<<<dim3(E_ / ET, M_ / (MT * TILES)), 256, SMEM_BYTES>>>(bias, pos, out);
}

// round 15
// speedup vs baseline: 1.1629x; 1.0032x over previous
#include <cuda_runtime.h>
#include <cuda_fp16.h>
#include <cstdint>

// ---------------------------------------------------------------- constants
#define B_     64
#define T_     16
#define IMG_   84
#define FR_    7056         // 84*84
#define P_     7
#define NS_    144
#define K_     98
#define KP_    128          // physical row width (halves)
#define KSTEPS 6            // tensor path: 6 x k16 = 96; k=96,97 via FFMA
#define E_     1024
#define NTOK_  1152
#define M_     73728

// Swizzled scratch: within each 128-half row, 16B chunk c lives at c ^ (row&7).
__device__ __half g_A[(size_t)M_ * KP_];   // [m][128]  18.9 MB
__device__ __half g_B[(size_t)E_ * KP_];   // [e][128]  256 KB

// ---------------------------------------------------------------- helpers
__device__ __forceinline__ void mma_f16(float4& d, const uint32_t a[4],
                                        const uint32_t b[2]) {
    asm("mma.sync.aligned.m16n8k16.row.col.f32.f16.f16.f32 "
        "{%0,%1,%2,%3}, {%4,%5,%6,%7}, {%8,%9}, {%0,%1,%2,%3};"
        : "+f"(d.x), "+f"(d.y), "+f"(d.z), "+f"(d.w)
        : "r"(a[0]), "r"(a[1]), "r"(a[2]), "r"(a[3]), "r"(b[0]), "r"(b[1]));
}
__device__ __forceinline__ void ldsm_x4(uint32_t a[4], uint32_t addr) {
    asm volatile("ldmatrix.sync.aligned.m8n8.x4.shared.b16 {%0,%1,%2,%3}, [%4];"
                 : "=r"(a[0]), "=r"(a[1]), "=r"(a[2]), "=r"(a[3]) : "r"(addr));
}
__device__ __forceinline__ uint32_t smem_u32(const void* p) {
    uint32_t a;
    asm("{ .reg .u64 t; cvta.to.shared.u64 t, %1; cvt.u32.u64 %0, t; }"
        : "=r"(a) : "l"(p));
    return a;
}
#define MBAR_INIT(mb, c) \
    asm volatile("mbarrier.init.shared.b64 [%0], %1;" \
                 :: "r"((uint32_t)(mb)), "r"((uint32_t)(c)) : "memory")
#define MBAR_EXPECT_TX(mb, n) \
    asm volatile("mbarrier.arrive.expect_tx.shared.b64 _, [%0], %1;" \
                 :: "r"((uint32_t)(mb)), "r"((uint32_t)(n)) : "memory")
#define MBAR_WAIT(mb, ph) do {                                                    \
    uint32_t _mb = (uint32_t)(mb); uint32_t _ph = (uint32_t)(ph); uint32_t _done; \
    asm volatile("{\n\t.reg .pred p;\n\t"                                         \
        "mbarrier.try_wait.parity.acquire.cta.shared::cta.b64 p, [%1], %2;\n\t"   \
        "selp.b32 %0, 1, 0, p;\n\t}" : "=r"(_done) : "r"(_mb), "r"(_ph) : "memory"); \
    if (!_done) {                                                                 \
        asm volatile("{\n\t.reg .pred P1;\n\t"                                    \
            "WL_%=:\n\t"                                                          \
            "mbarrier.try_wait.parity.acquire.cta.shared::cta.b64 P1, [%0], %1, 0x989680;\n\t" \
            "@P1 bra.uni WD_%=;\n\t"                                              \
            "bra.uni WL_%=;\n\t"                                                  \
            "WD_%=:\n\t}" :: "r"(_mb), "r"(_ph) : "memory");                      \
    }                                                                             \
} while (0)
__device__ __forceinline__ void bulk_g2s(uint32_t dst, const void* src,
                                         uint32_t bytes, uint32_t mbar) {
    asm volatile(
        "cp.async.bulk.shared::cta.global.mbarrier::complete_tx::bytes "
        "[%0], [%1], %2, [%3];"
        :: "r"(dst), "l"(src), "r"(bytes), "r"(mbar) : "memory");
}

// ---------------------------------------------------------------- prep
#define GROWS 42
#define GHALF (GROWS * IMG_)   // 3528 pixels
__global__ void prep_kernel(const float* __restrict__ video,
                            const float* __restrict__ W) {
    int blk = blockIdx.x;
    if (blk >= 1024) {                        // ---- W conversion ----
        for (int idx = (blk - 1024) * 256 + threadIdx.x; idx < E_ * K_;
             idx += 32 * 256) {
            int e = idx / K_, k = idx - e * K_;
            int ph = (((k >> 3) ^ (e & 7)) << 3) | (k & 7);
            g_B[(size_t)e * KP_ + ph] = __float2half_rn(W[idx]);
        }
        return;
    }
    // ---- gather ----
    extern __shared__ __half fr[];            // [2][GHALF]
    int b = blk >> 4, dh = blk & 15;
    int d = dh >> 1, half = dh & 1;
    const float* src = video + (size_t)(b * T_ + d * 2) * FR_ + half * GHALF;
    for (int i = threadIdx.x; i < (2 * GHALF) / 4; i += blockDim.x) {
        int f = i / (GHALF / 4);
        int j = i - f * (GHALF / 4);
        float4 v = *(const float4*)(src + (size_t)f * FR_ + j * 4);
        __half h[4] = {__float2half_rn(v.x), __float2half_rn(v.y),
                       __float2half_rn(v.z), __float2half_rn(v.w)};
        *(uint2*)(&fr[f * GHALF + j * 4]) = *(const uint2*)h;
    }
    __syncthreads();

    int mbase = b * NTOK_ + d * NS_;
    for (int u = threadIdx.x; u < 72 * 13; u += blockDim.x) {
        int sl = u / 13, c = u - sl * 13;
        int s  = half * 72 + sl;
        int hl = sl / 12, w = sl - hl * 12;
        const __half* f0 = fr + hl * (P_ * IMG_) + w * P_;
        __half hv[8];
#pragma unroll
        for (int j = 0; j < 8; ++j) {
            int kk = c * 8 + j;
            __half v = __ushort_as_half((unsigned short)0);
            if (kk < K_) {
                int ts = kk >= 49;
                int k  = kk - ts * 49;
                int pi = k / P_, pj = k - pi * P_;
                v = f0[ts * GHALF + pi * IMG_ + pj];
            }
            hv[j] = v;
        }
        int ph = c ^ (s & 7);
        *(uint4*)(&g_A[(size_t)(mbase + s) * KP_ + ph * 8]) = *(const uint4*)hv;
    }
}

// ---------------------------------------------------------------- GEMM
// Persistent-strip GEMM: grid 8(e) x 18(strips). B loaded once; 16 m-tiles of
// 256x128 double-buffered via bulk copies. Warp tile 64x64 in ONE pass
// (acc[4][8], A fragments read once, B via LDSM.x4 pairs). Epilogue staged
// through the (now idle) A buffer with an XOR swizzle so pos loads and out
// stores are fully 128B-coalesced.
#define MT      256
#define ET      128
#define TILES   16
#define SBB     (ET * KP_)              // B halves (32 KB)
#define SAB     (MT * KP_)              // A halves per buffer (64 KB)
#define ATILE_BYTES (SAB * 2)
#define SMEM_BYTES ((SBB + 2 * SAB) * 2)   // 163840 B

__global__ __launch_bounds__(256, 1)
void gemm_kernel(const float* __restrict__ bias,
                 const float* __restrict__ pos,
                 float* __restrict__ out) {
    extern __shared__ __half sm[];
    __half* sB = sm;                   // [128][128] swizzled rows
    __half* sA0 = sm + SBB;
    __half* sA1 = sA0 + SAB;
    __shared__ __align__(8) unsigned long long bars[3];  // B, A0, A1

    const int tid  = threadIdx.x;
    const int lane = tid & 31;
    const int wid  = tid >> 5;
    const int grp  = lane >> 2;        // 0..7
    const int tg   = lane & 3;         // 0..3
    const int wm   = wid & 3;          // m-quarter -> wm*64
    const int wn   = wid >> 2;         // e-half    -> wn*64

    const int e0 = blockIdx.x * ET;
    const int j0 = blockIdx.y * TILES;

    const uint32_t barB  = smem_u32(&bars[0]);
    const uint32_t barA0 = smem_u32(&bars[1]);
    const uint32_t barA1 = smem_u32(&bars[2]);

    if (tid == 0) {
        MBAR_INIT(barB, 1);
        MBAR_INIT(barA0, 1);
        MBAR_INIT(barA1, 1);
    }
    __syncthreads();

    if (tid == 0) {
        MBAR_EXPECT_TX(barB, SBB * 2);
        bulk_g2s(smem_u32(sB), g_B + (size_t)e0 * KP_, SBB * 2, barB);
        MBAR_EXPECT_TX(barA0, ATILE_BYTES);
        bulk_g2s(smem_u32(sA0), g_A + (size_t)j0 * MT * KP_, ATILE_BYTES, barA0);
        MBAR_EXPECT_TX(barA1, ATILE_BYTES);
        bulk_g2s(smem_u32(sA1), g_A + (size_t)(j0 + 1) * MT * KP_, ATILE_BYTES, barA1);
    }

    // ldmatrix per-lane address components
    const int aql  = lane & 7;
    const int aqm  = ((lane >> 3) & 1) * 8;
    const int akc  = lane >> 4;                  // A k8-chunk 0/1
    const uint32_t arl16 = (uint32_t)aql << 4;
    // B x4: matrices (rows nf2*16+{0..7}, k0), (rows +0, k1), (rows +8, k0), (rows +8, k1)
    const uint32_t uB4 = smem_u32(sB) +
        (uint32_t)(wn * 64 + ((lane >> 4) & 1) * 8 + (lane & 7)) * (KP_ * 2);
    const int bkc4 = (lane >> 3) & 1;
    const uint32_t brl16 = (uint32_t)(lane & 7) << 4;

    MBAR_WAIT(barB, 0);

#pragma unroll 1
    for (int i = 0; i < TILES; ++i) {
        const int buf = i & 1;
        const uint32_t barA = buf ? barA1 : barA0;
        __half* sA = buf ? sA1 : sA0;
        MBAR_WAIT(barA, (i >> 1) & 1);

        const int m0 = (j0 + i) * MT;
        const int n0 = m0 % NTOK_;
        const __half* wAp = sA + (wm * 64 + grp) * KP_;    // FFMA-tail A ptr
        const uint32_t uA = smem_u32(sA) +
            (uint32_t)(wm * 64 + aqm + aql) * (KP_ * 2);

        // A operands for the k=96,97 FFMA tail (chunk 12)
        float2 ca0[4], ca1[4];
        {
            const int ca = (12 ^ grp) << 3;
#pragma unroll
            for (int mf = 0; mf < 4; ++mf) {
                ca0[mf] = __half22float2(*(const __half2*)(wAp + mf * 16 * KP_ + ca));
                ca1[mf] = __half22float2(*(const __half2*)(wAp + (mf * 16 + 8) * KP_ + ca));
            }
        }

        float4 acc[4][8];
#pragma unroll
        for (int a = 0; a < 4; ++a)
#pragma unroll
            for (int b = 0; b < 8; ++b) acc[a][b] = make_float4(0.f, 0.f, 0.f, 0.f);

#pragma unroll
        for (int ks = 0; ks < KSTEPS; ++ks) {
            const uint32_t offA = (uint32_t)((2 * ks + akc) << 4) ^ arl16;
            const uint32_t offB = (uint32_t)((2 * ks + bkc4) << 4) ^ brl16;

            uint32_t af[4][4], bf[8][2];
#pragma unroll
            for (int mf = 0; mf < 4; ++mf)
                ldsm_x4(af[mf], uA + (uint32_t)mf * (16 * KP_ * 2) + offA);
#pragma unroll
            for (int nf2 = 0; nf2 < 4; ++nf2) {
                uint32_t r4[4];
                ldsm_x4(r4, uB4 + (uint32_t)nf2 * (16 * KP_ * 2) + offB);
                bf[nf2 * 2][0]     = r4[0];
                bf[nf2 * 2][1]     = r4[1];
                bf[nf2 * 2 + 1][0] = r4[2];
                bf[nf2 * 2 + 1][1] = r4[3];
            }
#pragma unroll
            for (int mf = 0; mf < 4; ++mf)
#pragma unroll
                for (int nf = 0; nf < 8; ++nf)
                    mma_f16(acc[mf][nf], af[mf], bf[nf]);
        }

        // FFMA tail: kk = 96,97 on the fp32 pipe
#pragma unroll
        for (int nf = 0; nf < 8; ++nf) {
            int er = wn * 64 + nf * 8 + 2 * tg;
            const __half* bp0 = sB + (size_t)er * KP_ + ((12 ^ (er & 7)) << 3);
            const __half* bp1 = sB + (size_t)(er + 1) * KP_ + ((12 ^ ((er + 1) & 7)) << 3);
            float2 b0 = __half22float2(*(const __half2*)bp0);
            float2 b1 = __half22float2(*(const __half2*)bp1);
#pragma unroll
            for (int mf = 0; mf < 4; ++mf) {
                float4& a = acc[mf][nf];
                a.x += ca0[mf].x * b0.x + ca0[mf].y * b0.y;
                a.y += ca0[mf].x * b1.x + ca0[mf].y * b1.y;
                a.z += ca1[mf].x * b0.x + ca1[mf].y * b0.y;
                a.w += ca1[mf].x * b1.x + ca1[mf].y * b1.y;
            }
        }

        // ---- staged epilogue: acc -> swizzled sD (reuses THIS tile's A buf,
        //      dead until the i+2 prefetch) -> coalesced 128B loads/stores ----
        float* sD = (float*)sA;        // [128 rows][128 words], 16B chunk swizzle
#pragma unroll
        for (int r = 0; r < 2; ++r) {
            __syncthreads();           // round 0: also guards sA fragment reads
#pragma unroll
            for (int mfp = 0; mfp < 2; ++mfp) {
                const int mf = 2 * r + mfp;
                const int rx0 = wm * 32 + mfp * 16 + grp;
                const int rx1 = rx0 + 8;
#pragma unroll
                for (int nf = 0; nf < 8; ++nf) {
                    int chunk = wn * 16 + nf * 2 + (tg >> 1);
                    int w0 = (tg & 1) * 2;
                    int pc0 = (chunk & 24) | ((chunk ^ rx0) & 7);
                    int pc1 = (chunk & 24) | ((chunk ^ rx1) & 7);
                    *(float2*)&sD[rx0 * 128 + pc0 * 4 + w0] =
                        make_float2(acc[mf][nf].x, acc[mf][nf].y);
                    *(float2*)&sD[rx1 * 128 + pc1 * 4 + w0] =
                        make_float2(acc[mf][nf].z, acc[mf][nf].w);
                }
            }
            __syncthreads();
            // reader: warp w -> slab rows [w*16, w*16+16); 4 rows per instr,
            // 8 lanes cover one 128B segment -> fully coalesced LDG/STG.
#pragma unroll
            for (int g = 0; g < 4; ++g) {
                const int ridx = wid * 16 + g * 4 + (lane >> 3);
                const int mfd  = 2 * r + ((ridx >> 4) & 1);
                const int mloc = (ridx >> 5) * 64 + mfd * 16 + (ridx & 15);
                const int m = m0 + mloc;
                int n = n0 + mloc; if (n >= NTOK_) n -= NTOK_;
                const float* pr = pos + (size_t)n * E_;
                float* orow = out + (size_t)m * E_;
#pragma unroll
                for (int ph = 0; ph < 4; ++ph) {
                    int pc  = (ph * 8) | (((lane & 7) ^ ridx) & 7);
                    float4 v = *(const float4*)&sD[ridx * 128 + pc * 4];
                    int col = e0 + (ph * 8 + (lane & 7)) * 4;
                    float4 bb4 = *(const float4*)&bias[col];
                    float4 pp4 = *(const float4*)&pr[col];
                    float4 o = make_float4(v.x + bb4.x + pp4.x,
                                           v.y + bb4.y + pp4.y,
                                           v.z + bb4.z + pp4.z,
                                           v.w + bb4.w + pp4.w);
                    __stcs((float4*)&orow[col], o);
                }
            }
        }

        // all reads of buffer `buf` done -> refill it 2 tiles ahead
        __syncthreads();
        if (tid == 0 && i + 2 < TILES) {
            MBAR_EXPECT_TX(barA, ATILE_BYTES);
            bulk_g2s(smem_u32(sA), g_A + (size_t)(j0 + i + 2) * MT * KP_,
                     ATILE_BYTES, barA);
        }
    }
}

// ---------------------------------------------------------------- launch
extern "C" void kernel_launch(void* const* d_in, const int* in_sizes, int n_in,
                              void* d_out, int out_size) {
    const float* video = (const float*)d_in[0];   // [64,16,1,84,84]
    const float* W     = (const float*)d_in[1];   // [1024,98]
    const float* bias  = (const float*)d_in[2];   // [1024]
    const float* pos   = (const float*)d_in[3];   // [1,1152,1024]
    float* out         = (float*)d_out;           // [64,1152,1024]

    cudaFuncSetAttribute(gemm_kernel, cudaFuncAttributeMaxDynamicSharedMemorySize,
                         SMEM_BYTES);
    cudaFuncSetAttribute(prep_kernel, cudaFuncAttributeMaxDynamicSharedMemorySize,
                         2 * GHALF * 2);

    prep_kernel<<<1024 + 32, 256, 2 * GHALF * 2>>>(video, W);
    gemm_kernel<<<dim3(E_ / ET, M_ / (MT * TILES)), 256, SMEM_BYTES>>>(bias, pos, out);
}